// round 1
// baseline (speedup 1.0000x reference)
#include <cuda_runtime.h>

#define LOG_CLAMP -100.0f

// total elements: 64 * 8 * 65536 = 33,554,432 (divisible by 4)
__global__ void vloss_init(float* out) {
    *out = 0.0f;
}

__global__ void __launch_bounds__(256)
vloss_main(const float* __restrict__ pred,
           const float* __restrict__ tru,
           float* __restrict__ out,
           int n4, float inv_scale) {
    const float4* p4 = reinterpret_cast<const float4*>(pred);
    const float4* t4 = reinterpret_cast<const float4*>(tru);

    float acc = 0.0f;
    int stride = gridDim.x * blockDim.x;
    for (int i = blockIdx.x * blockDim.x + threadIdx.x; i < n4; i += stride) {
        float4 p = p4[i];
        float4 t = t4[i];

        float lp0 = fmaxf(logf(p.x), LOG_CLAMP);
        float lq0 = fmaxf(log1pf(-p.x), LOG_CLAMP);
        float lp1 = fmaxf(logf(p.y), LOG_CLAMP);
        float lq1 = fmaxf(log1pf(-p.y), LOG_CLAMP);
        float lp2 = fmaxf(logf(p.z), LOG_CLAMP);
        float lq2 = fmaxf(log1pf(-p.z), LOG_CLAMP);
        float lp3 = fmaxf(logf(p.w), LOG_CLAMP);
        float lq3 = fmaxf(log1pf(-p.w), LOG_CLAMP);

        // bce = -(t*lp + (1-t)*lq) = -(lq + t*(lp - lq))
        acc -= lq0 + t.x * (lp0 - lq0);
        acc -= lq1 + t.y * (lp1 - lq1);
        acc -= lq2 + t.z * (lp2 - lq2);
        acc -= lq3 + t.w * (lp3 - lq3);
    }

    // warp reduce
    #pragma unroll
    for (int off = 16; off > 0; off >>= 1)
        acc += __shfl_down_sync(0xFFFFFFFFu, acc, off);

    __shared__ float warp_sums[8];  // 256 threads = 8 warps
    int lane = threadIdx.x & 31;
    int wid  = threadIdx.x >> 5;
    if (lane == 0) warp_sums[wid] = acc;
    __syncthreads();

    if (wid == 0) {
        float v = (lane < 8) ? warp_sums[lane] : 0.0f;
        #pragma unroll
        for (int off = 4; off > 0; off >>= 1)
            v += __shfl_down_sync(0xFFFFFFFFu, v, off);
        if (lane == 0)
            atomicAdd(out, v * inv_scale);
    }
}

extern "C" void kernel_launch(void* const* d_in, const int* in_sizes, int n_in,
                              void* d_out, int out_size) {
    const float* pred = (const float*)d_in[0];
    const float* tru  = (const float*)d_in[1];
    float* out = (float*)d_out;

    int n = in_sizes[0];               // 33,554,432
    int n4 = n >> 2;                   // float4 count
    // divisor: H * B = 65536 * 64
    float inv_scale = 1.0f / (65536.0f * 64.0f);

    vloss_init<<<1, 1>>>(out);

    int threads = 256;
    int blocks = 148 * 8;              // 1184 blocks, ~28 float4/thread
    vloss_main<<<blocks, threads>>>(pred, tru, out, n4, inv_scale);
}

// round 2
// speedup vs baseline: 1.6412x; 1.6412x over previous
#include <cuda_runtime.h>

// Work in log2 units; clamp -100 (nat log) = -100/ln2 in log2 units.
#define LG2_CLAMP (-144.26950408889634f)
#define LN2       (0.6931471805599453f)

__global__ void vloss_init(float* out) {
    *out = 0.0f;
}

__device__ __forceinline__ float lg2_fast(float x) {
    float r;
    asm("lg2.approx.f32 %0, %1;" : "=f"(r) : "f"(x));
    return r;
}

__global__ void __launch_bounds__(256)
vloss_main(const float* __restrict__ pred,
           const float* __restrict__ tru,
           float* __restrict__ out,
           int n4, float inv_scale) {
    const float4* p4 = reinterpret_cast<const float4*>(pred);
    const float4* t4 = reinterpret_cast<const float4*>(tru);

    float acc = 0.0f;
    int stride = gridDim.x * blockDim.x;
    for (int i = blockIdx.x * blockDim.x + threadIdx.x; i < n4; i += stride) {
        float4 p = p4[i];
        float4 t = t4[i];

        float lp0 = fmaxf(lg2_fast(p.x),        LG2_CLAMP);
        float lq0 = fmaxf(lg2_fast(1.0f - p.x), LG2_CLAMP);
        float lp1 = fmaxf(lg2_fast(p.y),        LG2_CLAMP);
        float lq1 = fmaxf(lg2_fast(1.0f - p.y), LG2_CLAMP);
        float lp2 = fmaxf(lg2_fast(p.z),        LG2_CLAMP);
        float lq2 = fmaxf(lg2_fast(1.0f - p.z), LG2_CLAMP);
        float lp3 = fmaxf(lg2_fast(p.w),        LG2_CLAMP);
        float lq3 = fmaxf(lg2_fast(1.0f - p.w), LG2_CLAMP);

        // bce (in log2 units) = -(lq + t*(lp - lq)); ln2 folded into final scale
        acc -= lq0 + t.x * (lp0 - lq0);
        acc -= lq1 + t.y * (lp1 - lq1);
        acc -= lq2 + t.z * (lp2 - lq2);
        acc -= lq3 + t.w * (lp3 - lq3);
    }

    // warp reduce
    #pragma unroll
    for (int off = 16; off > 0; off >>= 1)
        acc += __shfl_down_sync(0xFFFFFFFFu, acc, off);

    __shared__ float warp_sums[8];
    int lane = threadIdx.x & 31;
    int wid  = threadIdx.x >> 5;
    if (lane == 0) warp_sums[wid] = acc;
    __syncthreads();

    if (wid == 0) {
        float v = (lane < 8) ? warp_sums[lane] : 0.0f;
        #pragma unroll
        for (int off = 4; off > 0; off >>= 1)
            v += __shfl_down_sync(0xFFFFFFFFu, v, off);
        if (lane == 0)
            atomicAdd(out, v * inv_scale);
    }
}

extern "C" void kernel_launch(void* const* d_in, const int* in_sizes, int n_in,
                              void* d_out, int out_size) {
    const float* pred = (const float*)d_in[0];
    const float* tru  = (const float*)d_in[1];
    float* out = (float*)d_out;

    int n = in_sizes[0];               // 33,554,432
    int n4 = n >> 2;
    // divisor: H * B = 65536 * 64; multiply by ln2 to convert log2 -> ln
    float inv_scale = LN2 / (65536.0f * 64.0f);

    vloss_init<<<1, 1>>>(out);

    int threads = 256;
    int blocks = 148 * 16;             // 2368 blocks
    vloss_main<<<blocks, threads>>>(pred, tru, out, n >> 2 == n4 ? n4 : n4, inv_scale);
}